// round 1
// baseline (speedup 1.0000x reference)
#include <cuda_runtime.h>
#include <cuda_bf16.h>
#include <cstdint>

#define R 512
#define T 65536
#define KMAX 64     // ELL storage capacity per row (safety; expected ~5, max ~15)
#define KREG 20     // register-resident ELL entries per thread

// ---------------- device scratch (static allocation is allowed) ----------------
__device__ float g_val[KMAX * R];     // interleaved [k][row]
__device__ int   g_col[KMAX * R];     // interleaved [k][row]
__device__ int   g_len[R];
__device__ float g_states[(size_t)T * R];   // 128 MB state trace

// ---------------- Kernel A: extract sparse structure of W ----------------
__global__ void __launch_bounds__(R, 1) esn_extract(const float* __restrict__ W) {
    int i = threadIdx.x;           // row
    int len = 0;
    for (int j = 0; j < R; ++j) {
        float v = W[i * R + j];
        if (v != 0.0f) {
            if (len < KMAX) {
                g_val[len * R + i] = v;
                g_col[len * R + i] = j;
            }
            ++len;
        }
    }
    g_len[i] = (len < KMAX) ? len : KMAX;
}

// fast-but-accurate tanh: 1 - 2/(e^{2x}+1); ~1e-6 abs err, saturates correctly
__device__ __forceinline__ float tanh_acc(float x) {
    float e = __expf(2.0f * x);
    return 1.0f - __fdividef(2.0f, e + 1.0f);
}

// ---------------- Kernel B: sequential recurrence, 1 CTA, 512 threads ----------------
__global__ void __launch_bounds__(R, 1) esn_recur(
    const float* __restrict__ x,      // [T,2]
    const float* __restrict__ h0,     // [512]
    const float* __restrict__ Win,    // [512,2]
    float*       __restrict__ hfinal, // [512] or nullptr
    int write_hfinal)
{
    __shared__ float hbuf[2][R];
    const int i = threadIdx.x;

    const int len = g_len[i];

    // register-resident ELL (compile-time indexed -> stays in registers)
    float rv[KREG];
    int   rc[KREG];
#pragma unroll
    for (int k = 0; k < KREG; ++k) {
        rv[k] = g_val[k * R + i];   // garbage beyond len is never used (predicated)
        rc[k] = g_col[k * R + i];
    }

    const float w0 = Win[i * 2 + 0];
    const float w1 = Win[i * 2 + 1];

    hbuf[0][i] = h0[i];
    __syncthreads();

    const float2* __restrict__ xx = (const float2*)x;

    float hn = 0.0f;
    for (int t = 0; t < T; ++t) {
        const int p = t & 1;
        const float* hr = hbuf[p];

        float2 xv = xx[t];                       // broadcast load (same addr all lanes)
        float acc = w0 * xv.x + w1 * xv.y;

#pragma unroll
        for (int k = 0; k < KREG; ++k)
            if (k < len)
                acc += rv[k] * hr[rc[k]];

        // overflow fallback (essentially never taken; guarantees correctness)
        for (int k = KREG; k < len; ++k)
            acc += g_val[k * R + i] * hr[g_col[k * R + i]];

        hn = tanh_acc(acc);

        hbuf[p ^ 1][i] = hn;
        g_states[(size_t)t * R + i] = hn;        // fire-and-forget
        __syncthreads();
    }

    if (write_hfinal) hfinal[i] = hn;
}

// ---------------- Kernel C: readout GEMV, warp per timestep ----------------
__global__ void __launch_bounds__(256) esn_readout(
    const float* __restrict__ Wout,   // [2,512]
    const float* __restrict__ bias,   // [2]
    float*       __restrict__ out)    // [T,2]
{
    __shared__ float w0s[R];
    __shared__ float w1s[R];
    const int tid = threadIdx.x;
    for (int j = tid; j < R; j += 256) {
        w0s[j] = Wout[j];
        w1s[j] = Wout[R + j];
    }
    __syncthreads();

    const int warp = tid >> 5;
    const int lane = tid & 31;
    const size_t t = (size_t)blockIdx.x * 8 + warp;   // 8 warps/block
    if (t >= T) return;

    const float* __restrict__ s = g_states + t * R;
    float a0 = 0.0f, a1 = 0.0f;
#pragma unroll
    for (int k = 0; k < R / 32; ++k) {
        int j = lane + 32 * k;
        float v = s[j];                     // coalesced 128B/iter
        a0 += v * w0s[j];
        a1 += v * w1s[j];
    }
#pragma unroll
    for (int o = 16; o; o >>= 1) {
        a0 += __shfl_down_sync(0xFFFFFFFFu, a0, o);
        a1 += __shfl_down_sync(0xFFFFFFFFu, a1, o);
    }
    if (lane == 0) {
        out[2 * t + 0] = a0 + bias[0];
        out[2 * t + 1] = a1 + bias[1];
    }
}

// ---------------- launch ----------------
extern "C" void kernel_launch(void* const* d_in, const int* in_sizes, int n_in,
                              void* d_out, int out_size)
{
    const float* x     = (const float*)d_in[0];   // [1,T,2]
    const float* h0    = (const float*)d_in[1];   // [1,512]
    const float* Win   = (const float*)d_in[2];   // [512,2]
    const float* W     = (const float*)d_in[3];   // [512,512]
    const float* Wout  = (const float*)d_in[4];   // [2,512]
    const float* bias  = (const float*)d_in[5];   // [2]

    float* out = (float*)d_out;

    const int need_hf = (out_size >= T * 2 + R) ? 1 : 0;
    float* hfinal = out + (size_t)T * 2;

    esn_extract<<<1, R>>>(W);
    esn_recur<<<1, R>>>(x, h0, Win, need_hf ? hfinal : (float*)d_out, need_hf);
    esn_readout<<<(T + 7) / 8, 256>>>(Wout, bias, out);
}

// round 3
// speedup vs baseline: 1.2772x; 1.2772x over previous
#include <cuda_runtime.h>
#include <cuda_bf16.h>
#include <cstdint>

#define R 512
#define T 65536
#define KMAX 32      // storage capacity per row (Binomial(512,0.01): P(len>24) ~ 0)
#define CLSMAX 24    // largest register-resident class

// ---------------- device scratch ----------------
__device__ int   g_tcol[R * KMAX];      // [row][k] raw cols (phase1 temp)
__device__ float g_tval[R * KMAX];
__device__ float g_val[KMAX * R];       // [k][p] final ELL, permuted thread space
__device__ int   g_col[KMAX * R];       // [k][p] translated (sorted-space) col idx
__device__ int   g_rowof[R];            // thread p -> original row
__device__ int   g_plen[R];             // effective len per thread
__device__ int   g_wclass[R / 32];
__device__ float g_states[(size_t)T * R];   // 128 MB, PERMUTED state trace

// ---------------- Kernel A: extract + sort + bank-schedule ----------------
__global__ void __launch_bounds__(R, 1) esn_extract(const float* __restrict__ W) {
    __shared__ int s_len[R];
    __shared__ int s_pos[R];      // row -> sorted position
    __shared__ int s_rowof[R];    // sorted position -> row
    __shared__ int s_cnt[KMAX + 1];
    __shared__ int s_base[KMAX + 1];

    const int r = threadIdx.x;

    // phase 1: per-row nnz scan
    int len = 0;
    for (int j = 0; j < R; ++j) {
        float v = W[r * R + j];
        if (v != 0.0f) {
            if (len < KMAX) { g_tcol[r * KMAX + len] = j; g_tval[r * KMAX + len] = v; }
            ++len;
        }
    }
    if (len > KMAX) len = KMAX;
    s_len[r] = len;
    if (r <= KMAX) s_cnt[r] = 0;
    __syncthreads();

    // phase 2: counting sort by len (ascending)
    atomicAdd(&s_cnt[len], 1);
    __syncthreads();
    if (r == 0) {
        int acc = 0;
        for (int l = 0; l <= KMAX; ++l) { s_base[l] = acc; acc += s_cnt[l]; }
    }
    __syncthreads();
    int pos = atomicAdd(&s_base[len], 1);
    s_pos[r] = pos;
    s_rowof[pos] = r;
    __syncthreads();

    // phase 3: thread p builds its padded, bank-sorted, translated ELL slice
    const int p    = r;
    const int row  = s_rowof[p];
    const int mylen = s_len[row];
    const int wid  = p >> 5;
    const int Lw   = s_len[s_rowof[(wid << 5) | 31]];   // warp max (sorted ascending)
    int cls = (Lw + 1) & ~1;
    if (cls < 2) cls = 2;
    if (cls > CLSMAX) cls = CLSMAX;
    if ((p & 31) == 0) g_wclass[wid] = cls;
    g_rowof[p] = row;

    int   cols[KMAX];
    float vals[KMAX];
    for (int k = 0; k < mylen; ++k) {
        cols[k] = s_pos[g_tcol[row * KMAX + k]];   // translate to sorted space
        vals[k] = g_tval[row * KMAX + k];
    }
    int n = mylen;
    if (mylen <= cls) {
        for (int k = mylen; k < cls; ++k) { cols[k] = p; vals[k] = 0.0f; }  // own bank
        n = cls;
        // insertion-sort first n entries by ((bank - lane) & 31)
        const int lane = p & 31;
        for (int a = 1; a < n; ++a) {
            int  c = cols[a]; float v = vals[a];
            int  key = ((c & 31) - lane) & 31;
            int b = a - 1;
            while (b >= 0 && ((((cols[b] & 31) - lane) & 31) > key)) {
                cols[b + 1] = cols[b]; vals[b + 1] = vals[b]; --b;
            }
            cols[b + 1] = c; vals[b + 1] = v;
        }
    }
    for (int k = 0; k < n; ++k) {
        g_val[k * R + p] = vals[k];
        g_col[k * R + p] = cols[k];
    }
    g_plen[p] = n;
}

// accurate fast tanh: 1 - 2/(e^{2x}+1), ~1e-6 abs err
__device__ __forceinline__ float tanh_acc(float x) {
    float e = __expf(2.0f * x);
    return 1.0f - __fdividef(2.0f, e + 1.0f);
}

// ---------------- templated recurrence body ----------------
template <int NK>
__device__ __forceinline__ float run_loop(const float2* __restrict__ xx,
                                          float* __restrict__ hbuf,
                                          int p, int mylen, float w0, float w1)
{
    float rv[NK];
    int   rc[NK];   // byte offsets
#pragma unroll
    for (int k = 0; k < NK; ++k) {
        rv[k] = g_val[k * R + p];
        rc[k] = g_col[k * R + p] << 2;
    }

    float hn = 0.0f;
    for (int t = 0; t < T; ++t) {
        const char* hr = (const char*)(hbuf + ((t & 1) << 9));
        float2 xv = xx[t];
        float acc0 = w0 * xv.x;
        float acc1 = w1 * xv.y;
#pragma unroll
        for (int k = 0; k < NK; ++k) {
            float hv = *(const float*)(hr + rc[k]);
            if (k & 1) acc1 = fmaf(rv[k], hv, acc1);
            else       acc0 = fmaf(rv[k], hv, acc0);
        }
        if (NK < mylen) {   // safety path; never taken for this data
            for (int k = NK; k < mylen; ++k)
                acc0 = fmaf(g_val[k * R + p], ((const float*)hr)[g_col[k * R + p]], acc0);
        }
        hn = tanh_acc(acc0 + acc1);
        hbuf[(((t + 1) & 1) << 9) + p] = hn;          // coalesced (permuted space)
        g_states[(size_t)t * R + p] = hn;             // coalesced STG, fire-and-forget
        asm volatile("bar.sync 0;" ::: "memory");
    }
    return hn;
}

// ---------------- Kernel B: sequential recurrence, 1 CTA ----------------
__global__ void __launch_bounds__(R, 1) esn_recur(
    const float* __restrict__ x,
    const float* __restrict__ h0,
    const float* __restrict__ Win,
    float*       __restrict__ hfinal,
    int write_hfinal)
{
    __shared__ float hbuf[2 * R];
    const int p   = threadIdx.x;
    const int row = g_rowof[p];

    const float w0 = Win[row * 2 + 0];
    const float w1 = Win[row * 2 + 1];
    const int mylen = g_plen[p];
    const int cls   = g_wclass[p >> 5];

    hbuf[p] = h0[row];
    __syncthreads();

    const float2* xx = (const float2*)x;
    float hn;
    switch (cls) {
        case  2: hn = run_loop< 2>(xx, hbuf, p, mylen, w0, w1); break;
        case  4: hn = run_loop< 4>(xx, hbuf, p, mylen, w0, w1); break;
        case  6: hn = run_loop< 6>(xx, hbuf, p, mylen, w0, w1); break;
        case  8: hn = run_loop< 8>(xx, hbuf, p, mylen, w0, w1); break;
        case 10: hn = run_loop<10>(xx, hbuf, p, mylen, w0, w1); break;
        case 12: hn = run_loop<12>(xx, hbuf, p, mylen, w0, w1); break;
        case 14: hn = run_loop<14>(xx, hbuf, p, mylen, w0, w1); break;
        case 16: hn = run_loop<16>(xx, hbuf, p, mylen, w0, w1); break;
        case 18: hn = run_loop<18>(xx, hbuf, p, mylen, w0, w1); break;
        case 20: hn = run_loop<20>(xx, hbuf, p, mylen, w0, w1); break;
        case 22: hn = run_loop<22>(xx, hbuf, p, mylen, w0, w1); break;
        default: hn = run_loop<24>(xx, hbuf, p, mylen, w0, w1); break;
    }

    if (write_hfinal) hfinal[row] = hn;   // un-permute once
}

// ---------------- Kernel C: readout GEMV (permuted states) ----------------
__global__ void __launch_bounds__(256) esn_readout(
    const float* __restrict__ Wout,   // [2,512]
    const float* __restrict__ bias,   // [2]
    float*       __restrict__ out)    // [T,2]
{
    __shared__ float w0s[R];
    __shared__ float w1s[R];
    const int tid = threadIdx.x;
    for (int j = tid; j < R; j += 256) {
        int row = g_rowof[j];                 // states are permuted: weight[j] = Wout[row]
        w0s[j] = Wout[row];
        w1s[j] = Wout[R + row];
    }
    __syncthreads();

    const int warp = tid >> 5;
    const int lane = tid & 31;
    const size_t t = (size_t)blockIdx.x * 8 + warp;
    if (t >= T) return;

    const float* __restrict__ s = g_states + t * R;
    float a0 = 0.0f, a1 = 0.0f;
#pragma unroll
    for (int k = 0; k < R / 32; ++k) {
        int j = lane + 32 * k;
        float v = s[j];
        a0 += v * w0s[j];
        a1 += v * w1s[j];
    }
#pragma unroll
    for (int o = 16; o; o >>= 1) {
        a0 += __shfl_down_sync(0xFFFFFFFFu, a0, o);
        a1 += __shfl_down_sync(0xFFFFFFFFu, a1, o);
    }
    if (lane == 0) {
        out[2 * t + 0] = a0 + bias[0];
        out[2 * t + 1] = a1 + bias[1];
    }
}

// ---------------- launch ----------------
extern "C" void kernel_launch(void* const* d_in, const int* in_sizes, int n_in,
                              void* d_out, int out_size)
{
    const float* x    = (const float*)d_in[0];
    const float* h0   = (const float*)d_in[1];
    const float* Win  = (const float*)d_in[2];
    const float* W    = (const float*)d_in[3];
    const float* Wout = (const float*)d_in[4];
    const float* bias = (const float*)d_in[5];

    float* out = (float*)d_out;
    const int need_hf = (out_size >= T * 2 + R) ? 1 : 0;
    float* hfinal = out + (size_t)T * 2;

    esn_extract<<<1, R>>>(W);
    esn_recur<<<1, R>>>(x, h0, Win, need_hf ? hfinal : out, need_hf);
    esn_readout<<<(T + 7) / 8, 256>>>(Wout, bias, out);
}

// round 4
// speedup vs baseline: 1.4667x; 1.1484x over previous
#include <cuda_runtime.h>
#include <cuda_bf16.h>
#include <cstdint>

#define R 512
#define T 65536
#define KMAX 32      // per-row nnz cap AND max slot count (Binomial(512,0.01): P(len>24) ~ 0)

// ---------------- device scratch ----------------
__device__ int   g_tcol[R * KMAX];      // [row][k] raw cols (phase1)
__device__ float g_tval[R * KMAX];
__device__ int   g_pc[R * KMAX];        // [thread][k] translated cols (phase3)
__device__ float g_pv[R * KMAX];
__device__ float g_val[KMAX * R];       // [slot][thread] scheduled ELL
__device__ int   g_col[KMAX * R];
__device__ int   g_ovfcol[R * KMAX];    // overflow CSR (normally empty)
__device__ float g_ovfval[R * KMAX];
__device__ int   g_ovfcnt[R];
__device__ int   g_rowof[R];            // thread p -> original row
__device__ int   g_wclass[R / 32];
__device__ float g_states[(size_t)T * R];   // 128 MB, PERMUTED state trace

// ---------------- Kernel A: extract + length-sort + per-warp conflict-free slot schedule ----------------
__global__ void __launch_bounds__(R, 1) esn_extract(const float* __restrict__ W) {
    __shared__ int s_len[R];
    __shared__ int s_pos[R];
    __shared__ int s_rowof[R];
    __shared__ int s_cnt[KMAX + 1];
    __shared__ int s_base[KMAX + 1];

    const int p = threadIdx.x;

    // phase 1: per-row nnz scan (row = p)
    int len = 0;
    for (int j = 0; j < R; ++j) {
        float v = W[p * R + j];
        if (v != 0.0f) {
            if (len < KMAX) { g_tcol[p * KMAX + len] = j; g_tval[p * KMAX + len] = v; }
            ++len;
        }
    }
    if (len > KMAX) len = KMAX;
    s_len[p] = len;
    if (p <= KMAX) s_cnt[p] = 0;
    __syncthreads();

    // phase 2: counting sort by len (ascending) -> permutation
    atomicAdd(&s_cnt[len], 1);
    __syncthreads();
    if (p == 0) {
        int acc = 0;
        for (int l = 0; l <= KMAX; ++l) { s_base[l] = acc; acc += s_cnt[l]; }
    }
    __syncthreads();
    int pos = atomicAdd(&s_base[len], 1);
    s_pos[p] = pos;
    s_rowof[pos] = p;
    __syncthreads();

    // phase 3: thread p builds its translated entry list
    const int row   = s_rowof[p];
    const int mylen = s_len[row];
    g_rowof[p] = row;
    for (int k = 0; k < mylen; ++k) {
        g_pc[p * KMAX + k] = s_pos[g_tcol[row * KMAX + k]];
        g_pv[p * KMAX + k] = g_tval[row * KMAX + k];
    }
    g_ovfcnt[p] = 0;
    // stash own len in shared for lane0 (indexed by thread)
    s_len[p] = mylen;
    __syncthreads();

    // phase 4: lane 0 of each warp greedily schedules conflict-free slots
    if ((p & 31) == 0) {
        const int base = p;
        int      lens[32];
        unsigned taken[32];
        int total = 0;
        for (int i = 0; i < 32; ++i) {
            lens[i] = s_len[base + i];
            taken[i] = 0u;
            total += lens[i];
        }
        int s = 0;
        while (total > 0 && s < KMAX) {
            unsigned bankused = 0;
            int bankcol[32];
            int assigned[32];
            for (int i = 0; i < 32; ++i) {
                assigned[i] = -1;
                const int li = lens[i];
                for (int e = 0; e < li; ++e) {
                    if ((taken[i] >> e) & 1u) continue;
                    int c = g_pc[(base + i) * KMAX + e];
                    int b = c & 31;
                    bool free = !((bankused >> b) & 1u);
                    if (free || bankcol[b] == c) {   // free bank OR same-word broadcast
                        bankused |= 1u << b;
                        bankcol[b] = c;
                        taken[i] |= 1u << e;
                        assigned[i] = e;
                        --total;
                        break;
                    }
                }
            }
            int fb = 0;
            for (int i = 0; i < 32; ++i) {
                if (assigned[i] >= 0) {
                    int idx = (base + i) * KMAX + assigned[i];
                    g_col[s * R + base + i] = g_pc[idx];
                    g_val[s * R + base + i] = g_pv[idx];
                } else {
                    while ((bankused >> fb) & 1u) ++fb;   // provably enough free banks
                    bankused |= 1u << fb;
                    g_col[s * R + base + i] = fb;         // index fb -> bank fb, val 0
                    g_val[s * R + base + i] = 0.0f;
                }
            }
            ++s;
        }
        // leftovers (pathological only) -> per-thread overflow CSR
        if (total > 0) {
            for (int i = 0; i < 32; ++i) {
                int oc = 0;
                for (int e = 0; e < lens[i]; ++e) {
                    if (!((taken[i] >> e) & 1u)) {
                        g_ovfcol[(base + i) * KMAX + oc] = g_pc[(base + i) * KMAX + e];
                        g_ovfval[(base + i) * KMAX + oc] = g_pv[(base + i) * KMAX + e];
                        ++oc;
                    }
                }
                g_ovfcnt[base + i] = oc;
            }
        }
        int cls = (s + 1) & ~1;
        if (cls < 2) cls = 2;
        if (cls > KMAX) cls = KMAX;
        // pad rounding slots fully (lane i -> bank i: conflict-free)
        for (int ss = s; ss < cls; ++ss)
            for (int i = 0; i < 32; ++i) {
                g_col[ss * R + base + i] = i;
                g_val[ss * R + base + i] = 0.0f;
            }
        g_wclass[base >> 5] = cls;
    }
}

// accurate fast tanh: 1 - 2/(e^{2x}+1), ~1e-6 abs err
__device__ __forceinline__ float tanh_acc(float x) {
    float e = __expf(2.0f * x);
    return 1.0f - __fdividef(2.0f, e + 1.0f);
}

// ---------------- templated recurrence body ----------------
template <int NK>
__device__ __forceinline__ float run_loop(const float2* __restrict__ xx,
                                          float* __restrict__ hbuf,
                                          int p, int oc, float w0, float w1)
{
    float rv[NK];
    int   rc[NK];   // byte offsets
#pragma unroll
    for (int k = 0; k < NK; ++k) {
        rv[k] = g_val[k * R + p];
        rc[k] = g_col[k * R + p] << 2;
    }

    float* myst = g_states + p;
    float2 xv = xx[0];
    float hn = 0.0f;

    for (int t = 0; t < T; ++t) {
        const char* hr = (const char*)(hbuf + ((t & 1) << 9));
        float acc0 = w0 * xv.x;
        float acc1 = w1 * xv.y;
#pragma unroll
        for (int k = 0; k < NK; ++k) {
            float hv = *(const float*)(hr + rc[k]);
            if (k & 1) acc1 = fmaf(rv[k], hv, acc1);
            else       acc0 = fmaf(rv[k], hv, acc0);
        }
        if (oc) {   // warp-uniformly 0 in practice; correctness backstop
            for (int k = 0; k < oc; ++k)
                acc0 = fmaf(g_ovfval[p * KMAX + k],
                            ((const float*)hr)[g_ovfcol[p * KMAX + k]], acc0);
        }
        hn = tanh_acc(acc0 + acc1);
        hbuf[(((t + 1) & 1) << 9) + p] = hn;            // STS before arrive (BAR drains STS)

        asm volatile("bar.arrive 0, 1024;" ::: "memory");
        // off-critical-path work between arrive and wait:
        *myst = hn;  myst += R;                          // states STG, fire-and-forget
        int tn = (t + 1 < T) ? (t + 1) : (T - 1);
        xv = xx[tn];                                     // prefetch next x
        asm volatile("bar.sync 0, 1024;" ::: "memory");  // each warp arrives twice -> 1024
    }
    return hn;
}

// ---------------- Kernel B: sequential recurrence, 1 CTA ----------------
__global__ void __launch_bounds__(R, 1) esn_recur(
    const float* __restrict__ x,
    const float* __restrict__ h0,
    const float* __restrict__ Win,
    float*       __restrict__ hfinal,
    int write_hfinal)
{
    __shared__ float hbuf[2 * R];
    const int p   = threadIdx.x;
    const int row = g_rowof[p];

    const float w0 = Win[row * 2 + 0];
    const float w1 = Win[row * 2 + 1];
    const int oc  = g_ovfcnt[p];
    const int cls = g_wclass[p >> 5];

    hbuf[p] = h0[row];
    __syncthreads();

    const float2* xx = (const float2*)x;
    float hn;
    switch (cls) {
        case  2: hn = run_loop< 2>(xx, hbuf, p, oc, w0, w1); break;
        case  4: hn = run_loop< 4>(xx, hbuf, p, oc, w0, w1); break;
        case  6: hn = run_loop< 6>(xx, hbuf, p, oc, w0, w1); break;
        case  8: hn = run_loop< 8>(xx, hbuf, p, oc, w0, w1); break;
        case 10: hn = run_loop<10>(xx, hbuf, p, oc, w0, w1); break;
        case 12: hn = run_loop<12>(xx, hbuf, p, oc, w0, w1); break;
        case 14: hn = run_loop<14>(xx, hbuf, p, oc, w0, w1); break;
        case 16: hn = run_loop<16>(xx, hbuf, p, oc, w0, w1); break;
        case 18: hn = run_loop<18>(xx, hbuf, p, oc, w0, w1); break;
        case 20: hn = run_loop<20>(xx, hbuf, p, oc, w0, w1); break;
        case 22: hn = run_loop<22>(xx, hbuf, p, oc, w0, w1); break;
        case 24: hn = run_loop<24>(xx, hbuf, p, oc, w0, w1); break;
        case 26: hn = run_loop<26>(xx, hbuf, p, oc, w0, w1); break;
        case 28: hn = run_loop<28>(xx, hbuf, p, oc, w0, w1); break;
        case 30: hn = run_loop<30>(xx, hbuf, p, oc, w0, w1); break;
        default: hn = run_loop<32>(xx, hbuf, p, oc, w0, w1); break;
    }

    if (write_hfinal) hfinal[row] = hn;   // un-permute once
}

// ---------------- Kernel C: readout GEMV (permuted states) ----------------
__global__ void __launch_bounds__(256) esn_readout(
    const float* __restrict__ Wout,
    const float* __restrict__ bias,
    float*       __restrict__ out)
{
    __shared__ float w0s[R];
    __shared__ float w1s[R];
    const int tid = threadIdx.x;
    for (int j = tid; j < R; j += 256) {
        int row = g_rowof[j];
        w0s[j] = Wout[row];
        w1s[j] = Wout[R + row];
    }
    __syncthreads();

    const int warp = tid >> 5;
    const int lane = tid & 31;
    const size_t t = (size_t)blockIdx.x * 8 + warp;
    if (t >= T) return;

    const float* __restrict__ s = g_states + t * R;
    float a0 = 0.0f, a1 = 0.0f;
#pragma unroll
    for (int k = 0; k < R / 32; ++k) {
        int j = lane + 32 * k;
        float v = s[j];
        a0 += v * w0s[j];
        a1 += v * w1s[j];
    }
#pragma unroll
    for (int o = 16; o; o >>= 1) {
        a0 += __shfl_down_sync(0xFFFFFFFFu, a0, o);
        a1 += __shfl_down_sync(0xFFFFFFFFu, a1, o);
    }
    if (lane == 0) {
        out[2 * t + 0] = a0 + bias[0];
        out[2 * t + 1] = a1 + bias[1];
    }
}

// ---------------- launch ----------------
extern "C" void kernel_launch(void* const* d_in, const int* in_sizes, int n_in,
                              void* d_out, int out_size)
{
    const float* x    = (const float*)d_in[0];
    const float* h0   = (const float*)d_in[1];
    const float* Win  = (const float*)d_in[2];
    const float* W    = (const float*)d_in[3];
    const float* Wout = (const float*)d_in[4];
    const float* bias = (const float*)d_in[5];

    float* out = (float*)d_out;
    const int need_hf = (out_size >= T * 2 + R) ? 1 : 0;
    float* hfinal = out + (size_t)T * 2;

    esn_extract<<<1, R>>>(W);
    esn_recur<<<1, R>>>(x, h0, Win, need_hf ? hfinal : out, need_hf);
    esn_readout<<<(T + 7) / 8, 256>>>(Wout, bias, out);
}